// round 1
// baseline (speedup 1.0000x reference)
#include <cuda_runtime.h>
#include <math.h>

#define Bq  64
#define Lq  512
#define Dq  512
#define Wq  4
#define CUR 515   // L + W - 1

// ---------------------------------------------------------------------------
// Device-global scratch (allocation-free rule: __device__ arrays)
// ---------------------------------------------------------------------------
__device__ float g_F0 [Bq * Lq * Dq];   // masked F0
__device__ float g_F1 [Bq * Lq * Dq];   // masked F1
__device__ float g_A  [Bq * Lq * Lq];   // attention matrix A[b,i,j]
__device__ float g_F0a[Bq * Lq * Dq];   // A^T @ W0
__device__ float g_F1a[Bq * Lq * Dq];   // A  @ W1
__device__ float g_out0[Bq * CUR * Dq]; // conv+tanh outputs
__device__ float g_out1[Bq * CUR * Dq];
__device__ float g_n0 [Bq * Lq];        // sq-norms of F0 rows
__device__ float g_n1 [Bq * Lq];
__device__ float g_m0 [Bq * CUR];       // sq-norms of out0 rows
__device__ float g_m1 [Bq * CUR];
__device__ float g_a0 [Bq * CUR];       // row sums of A2
__device__ float g_a1 [Bq * CUR];       // col sums of A2

__device__ __forceinline__ float* buf_ptr(int id) {
    switch (id) {
        case 0:  return g_F0;
        case 1:  return g_F1;
        case 2:  return g_A;
        case 3:  return g_F0a;
        case 4:  return g_F1a;
        case 5:  return g_out0;
        case 6:  return g_out1;
        case 7:  return g_n0;
        case 8:  return g_n1;
        case 9:  return g_m0;
        case 10: return g_m1;
        case 11: return g_a0;
        case 12: return g_a1;
    }
    return nullptr;
}

// ---------------------------------------------------------------------------
// Kernel 0: apply mask, store masked features, compute per-row sq-norms
// grid (Lq, Bq, 2), block 128 (each thread handles 4 consecutive d via float4)
// ---------------------------------------------------------------------------
__global__ void mask_norm_kernel(const float* __restrict__ F0r,
                                 const float* __restrict__ F1r,
                                 const float* __restrict__ msk0,
                                 const float* __restrict__ msk1)
{
    const int i     = blockIdx.x;
    const int b     = blockIdx.y;
    const int which = blockIdx.z;

    const float* src = which ? F1r  : F0r;
    const float* msk = which ? msk1 : msk0;
    float*       dst = which ? g_F1 : g_F0;
    float*       nrm = which ? g_n1 : g_n0;

    const float m = msk[b * Lq + i];
    const long  base = ((long)b * Lq + i) * Dq + threadIdx.x * 4;

    float4 v = *(const float4*)(src + base);
    v.x *= m; v.y *= m; v.z *= m; v.w *= m;
    *(float4*)(dst + base) = v;

    float s = v.x * v.x + v.y * v.y + v.z * v.z + v.w * v.w;
#pragma unroll
    for (int off = 16; off > 0; off >>= 1)
        s += __shfl_xor_sync(0xffffffffu, s, off);

    __shared__ float red[4];
    const int lane = threadIdx.x & 31;
    const int wrp  = threadIdx.x >> 5;
    if (lane == 0) red[wrp] = s;
    __syncthreads();
    if (threadIdx.x == 0)
        nrm[b * Lq + i] = red[0] + red[1] + red[2] + red[3];
}

// ---------------------------------------------------------------------------
// Generic batched SGEMM, 128x128x8 tile, 256 threads, 8x8 per-thread microtile.
// AMODE/BMODE: 0 = global [m][k] (k contiguous, transpose-load into smem)
//              1 = global [k][m] (m contiguous, direct copy)
// EPI: 0 = plain store C
//      1 = distance epilogue: C = 1/(1+sqrt(max(rn+cn-2*acc,0)))
//      2 = distance + row/col-sum reduction (no C store), bounds-guarded M,N
// ---------------------------------------------------------------------------
template <int AMODE, int BMODE, int EPI>
__global__ __launch_bounds__(256, 2)
void gemm_kernel(int aId, const float* __restrict__ extA, int lda, long aBatch,
                 int bId, const float* __restrict__ extB, int ldb, long bBatch,
                 int cId, int ldc, long cBatch,
                 int M, int N,
                 int rnId, int rnStride, int cnId, int cnStride,
                 int rsId, int csId)
{
    __shared__ float As[8][128];
    __shared__ float Bs[8][128];

    const int bz = blockIdx.z;
    const int m0 = blockIdx.y * 128;
    const int n0 = blockIdx.x * 128;

    const float* A  = (aId >= 0 ? buf_ptr(aId) : extA) + (long)bz * aBatch;
    const float* Bm = (bId >= 0 ? buf_ptr(bId) : extB) + (long)bz * bBatch;

    const int tid = threadIdx.x;
    const int tx  = tid & 15;
    const int ty  = tid >> 4;

    float acc[8][8];
#pragma unroll
    for (int i = 0; i < 8; i++)
#pragma unroll
        for (int j = 0; j < 8; j++) acc[i][j] = 0.f;

    for (int k0 = 0; k0 < 512; k0 += 8) {
        if (AMODE == 0) {
            const int lr = tid >> 1;
            const int lk = (tid & 1) * 4;
            float4 v = make_float4(0.f, 0.f, 0.f, 0.f);
            if (m0 + lr < M)
                v = *(const float4*)(A + (long)(m0 + lr) * lda + k0 + lk);
            As[lk + 0][lr] = v.x; As[lk + 1][lr] = v.y;
            As[lk + 2][lr] = v.z; As[lk + 3][lr] = v.w;
        } else {
            const int lm = (tid & 31) * 4;
            const int lk = tid >> 5;
            *(float4*)&As[lk][lm] =
                *(const float4*)(A + (long)(k0 + lk) * lda + m0 + lm);
        }
        if (BMODE == 0) {
            const int lr = tid >> 1;
            const int lk = (tid & 1) * 4;
            float4 v = make_float4(0.f, 0.f, 0.f, 0.f);
            if (n0 + lr < N)
                v = *(const float4*)(Bm + (long)(n0 + lr) * ldb + k0 + lk);
            Bs[lk + 0][lr] = v.x; Bs[lk + 1][lr] = v.y;
            Bs[lk + 2][lr] = v.z; Bs[lk + 3][lr] = v.w;
        } else {
            const int ln = (tid & 31) * 4;
            const int lk = tid >> 5;
            *(float4*)&Bs[lk][ln] =
                *(const float4*)(Bm + (long)(k0 + lk) * ldb + n0 + ln);
        }
        __syncthreads();

#pragma unroll
        for (int kk = 0; kk < 8; kk++) {
            float af[8], bf[8];
            *(float4*)&af[0] = *(const float4*)&As[kk][ty * 4];
            *(float4*)&af[4] = *(const float4*)&As[kk][64 + ty * 4];
            *(float4*)&bf[0] = *(const float4*)&Bs[kk][tx * 4];
            *(float4*)&bf[4] = *(const float4*)&Bs[kk][64 + tx * 4];
#pragma unroll
            for (int i = 0; i < 8; i++)
#pragma unroll
                for (int j = 0; j < 8; j++)
                    acc[i][j] = fmaf(af[i], bf[j], acc[i][j]);
        }
        __syncthreads();
    }

    int rows[8], cols[8];
#pragma unroll
    for (int i = 0; i < 4; i++) {
        rows[i]     = m0 + ty * 4 + i;
        rows[4 + i] = m0 + 64 + ty * 4 + i;
        cols[i]     = n0 + tx * 4 + i;
        cols[4 + i] = n0 + 64 + tx * 4 + i;
    }

    if (EPI == 0) {
        float* C = buf_ptr(cId) + (long)bz * cBatch;
#pragma unroll
        for (int i = 0; i < 8; i++) {
            float4 v0 = make_float4(acc[i][0], acc[i][1], acc[i][2], acc[i][3]);
            float4 v1 = make_float4(acc[i][4], acc[i][5], acc[i][6], acc[i][7]);
            *(float4*)&C[(long)rows[i] * ldc + cols[0]] = v0;
            *(float4*)&C[(long)rows[i] * ldc + cols[4]] = v1;
        }
    } else if (EPI == 1) {
        const float* rn = buf_ptr(rnId) + (long)bz * rnStride;
        const float* cn = buf_ptr(cnId) + (long)bz * cnStride;
        float rv[8], cv[8];
#pragma unroll
        for (int i = 0; i < 8; i++) { rv[i] = rn[rows[i]]; cv[i] = cn[cols[i]]; }
        float* C = buf_ptr(cId) + (long)bz * cBatch;
#pragma unroll
        for (int i = 0; i < 8; i++) {
            float o[8];
#pragma unroll
            for (int j = 0; j < 8; j++) {
                float sq = rv[i] + cv[j] - 2.f * acc[i][j];
                float d  = sqrtf(fmaxf(sq, 0.f));
                o[j] = 1.f / (1.f + d);
            }
            *(float4*)&C[(long)rows[i] * ldc + cols[0]] =
                make_float4(o[0], o[1], o[2], o[3]);
            *(float4*)&C[(long)rows[i] * ldc + cols[4]] =
                make_float4(o[4], o[5], o[6], o[7]);
        }
    } else { // EPI == 2 : distance + row/col sums only
        const float* rn = buf_ptr(rnId) + (long)bz * rnStride;
        const float* cn = buf_ptr(cnId) + (long)bz * cnStride;
        float rv[8], cv[8];
#pragma unroll
        for (int i = 0; i < 8; i++) {
            rv[i] = (rows[i] < M) ? rn[rows[i]] : 0.f;
            cv[i] = (cols[i] < N) ? cn[cols[i]] : 0.f;
        }
        float rsumL[8], csumL[8];
#pragma unroll
        for (int i = 0; i < 8; i++) { rsumL[i] = 0.f; csumL[i] = 0.f; }
#pragma unroll
        for (int i = 0; i < 8; i++) {
            if (rows[i] < M) {
#pragma unroll
                for (int j = 0; j < 8; j++) {
                    if (cols[j] < N) {
                        float sq = rv[i] + cv[j] - 2.f * acc[i][j];
                        float d  = sqrtf(fmaxf(sq, 0.f));
                        float a2 = 1.f / (1.f + d);
                        rsumL[i] += a2;
                        csumL[j] += a2;
                    }
                }
            }
        }
        // reduce row sums across tx (16-lane half-warps share ty)
#pragma unroll
        for (int i = 0; i < 8; i++) {
#pragma unroll
            for (int s = 1; s < 16; s <<= 1)
                rsumL[i] += __shfl_xor_sync(0xffffffffu, rsumL[i], s);
        }
        float* srow = &As[0][0];        // 128 floats
        float* scol = &As[0][0] + 128;  // 128 floats
        if (tid < 128) scol[tid] = 0.f;
        __syncthreads();
        if (tx == 0) {
#pragma unroll
            for (int i = 0; i < 8; i++) srow[rows[i] - m0] = rsumL[i];
        }
#pragma unroll
        for (int j = 0; j < 8; j++)
            atomicAdd(&scol[cols[j] - n0], csumL[j]);
        __syncthreads();
        float* rs = buf_ptr(rsId) + (long)bz * CUR;
        float* cs = buf_ptr(csId) + (long)bz * CUR;
        if (tid < 128) {
            if (m0 + tid < M) atomicAdd(&rs[m0 + tid], srow[tid]);
        } else {
            const int t2 = tid - 128;
            if (n0 + t2 < N) atomicAdd(&cs[n0 + t2], scol[t2]);
        }
    }
}

// ---------------------------------------------------------------------------
// Kernel: fused width-4 2-channel conv + bias + tanh, plus row sq-norms
// grid (CUR, Bq, 2), block 128
// ---------------------------------------------------------------------------
__global__ void conv_tanh_kernel(const float* __restrict__ cw,
                                 const float* __restrict__ cb)
{
    const int t     = blockIdx.x;   // 0..CUR-1
    const int b     = blockIdx.y;
    const int which = blockIdx.z;

    const float* F   = which ? g_F1   : g_F0;
    const float* Fa  = which ? g_F1a  : g_F0a;
    float*       out = which ? g_out1 : g_out0;
    float*       mn  = which ? g_m1   : g_m0;

    float w0[4], w1[4];
#pragma unroll
    for (int k = 0; k < 4; k++) { w0[k] = cw[k]; w1[k] = cw[4 + k]; }
    const float bias = cb[0];

    const int d0 = threadIdx.x * 4;
    float4 acc = make_float4(bias, bias, bias, bias);
#pragma unroll
    for (int k = 0; k < 4; k++) {
        const int r = t + k - (Wq - 1);
        if (r >= 0 && r < Lq) {
            const long base = ((long)b * Lq + r) * Dq + d0;
            float4 f  = *(const float4*)(F  + base);
            float4 fa = *(const float4*)(Fa + base);
            acc.x = fmaf(w0[k], f.x, fmaf(w1[k], fa.x, acc.x));
            acc.y = fmaf(w0[k], f.y, fmaf(w1[k], fa.y, acc.y));
            acc.z = fmaf(w0[k], f.z, fmaf(w1[k], fa.z, acc.z));
            acc.w = fmaf(w0[k], f.w, fmaf(w1[k], fa.w, acc.w));
        }
    }
    acc.x = tanhf(acc.x); acc.y = tanhf(acc.y);
    acc.z = tanhf(acc.z); acc.w = tanhf(acc.w);
    *(float4*)(out + ((long)b * CUR + t) * Dq + d0) = acc;

    float s = acc.x * acc.x + acc.y * acc.y + acc.z * acc.z + acc.w * acc.w;
#pragma unroll
    for (int off = 16; off > 0; off >>= 1)
        s += __shfl_xor_sync(0xffffffffu, s, off);
    __shared__ float red[4];
    const int lane = threadIdx.x & 31;
    const int wrp  = threadIdx.x >> 5;
    if (lane == 0) red[wrp] = s;
    __syncthreads();
    if (threadIdx.x == 0)
        mn[b * CUR + t] = red[0] + red[1] + red[2] + red[3];
}

// ---------------------------------------------------------------------------
// Zero the A2 row/col sum accumulators
// ---------------------------------------------------------------------------
__global__ void zero_sums_kernel()
{
    const int i = blockIdx.x * blockDim.x + threadIdx.x;
    if (i < Bq * CUR) { g_a0[i] = 0.f; g_a1[i] = 0.f; }
}

// ---------------------------------------------------------------------------
// Final pool: o[b,t,d] = 0.25 * sum_{k<4} out[b,t+k,d] * a[b,t+k]
// grid (Lq, Bq, 2), block 128
// ---------------------------------------------------------------------------
__global__ void pool_kernel(float* __restrict__ outp)
{
    const int t     = blockIdx.x;   // 0..Lq-1
    const int b     = blockIdx.y;
    const int which = blockIdx.z;

    const float* src = which ? g_out1 : g_out0;
    const float* a   = which ? g_a1   : g_a0;

    const int d0 = threadIdx.x * 4;
    float4 acc = make_float4(0.f, 0.f, 0.f, 0.f);
#pragma unroll
    for (int k = 0; k < 4; k++) {
        const float w = a[b * CUR + t + k];
        float4 v = *(const float4*)(src + ((long)b * CUR + t + k) * Dq + d0);
        acc.x = fmaf(w, v.x, acc.x);
        acc.y = fmaf(w, v.y, acc.y);
        acc.z = fmaf(w, v.z, acc.z);
        acc.w = fmaf(w, v.w, acc.w);
    }
    acc.x *= 0.25f; acc.y *= 0.25f; acc.z *= 0.25f; acc.w *= 0.25f;

    float* dst = outp + (long)which * Bq * Lq * Dq + ((long)b * Lq + t) * Dq + d0;
    *(float4*)dst = acc;
}

// ---------------------------------------------------------------------------
// kernel_launch
// inputs: 0 F0r [B,L,D] | 1 F1r | 2 sent0_mask [B,L] | 3 sent1_mask
//         4 W0 [L,D] | 5 W1 | 6 conv_w [1,2,4,1] | 7 conv_b [1]
// output: o0 [B,L,D] then o1 [B,L,D], fp32
// ---------------------------------------------------------------------------
extern "C" void kernel_launch(void* const* d_in, const int* in_sizes, int n_in,
                              void* d_out, int out_size)
{
    const float* F0r  = (const float*)d_in[0];
    const float* F1r  = (const float*)d_in[1];
    const float* sm0  = (const float*)d_in[2];
    const float* sm1  = (const float*)d_in[3];
    const float* W0   = (const float*)d_in[4];
    const float* W1   = (const float*)d_in[5];
    const float* cw   = (const float*)d_in[6];
    const float* cb   = (const float*)d_in[7];
    float*       outp = (float*)d_out;

    // 1) masked features + row norms
    mask_norm_kernel<<<dim3(Lq, Bq, 2), 128>>>(F0r, F1r, sm0, sm1);

    // 2) A = 1/(1 + dist(F0, F1))   [NT gemm + distance epilogue]
    gemm_kernel<0, 0, 1><<<dim3(4, 4, Bq), 256>>>(
        0, nullptr, Dq, (long)Lq * Dq,     // A op: g_F0 [i][k]
        1, nullptr, Dq, (long)Lq * Dq,     // B op: g_F1 [j][k]
        2, Lq, (long)Lq * Lq,              // C: g_A [i][j]
        Lq, Lq,
        7, Lq, 8, Lq,                      // norms g_n0, g_n1
        -1, -1);

    // 3a) F0a = A^T @ W0   [TN gemm: A viewed [k=i][m=j] direct, W0 direct]
    gemm_kernel<1, 1, 0><<<dim3(4, 4, Bq), 256>>>(
        2, nullptr, Lq, (long)Lq * Lq,     // A op: g_A [i][j] as [k][m]
        -1, W0, Dq, 0L,                    // B op: W0 [i][d] as [k][n], shared
        3, Dq, (long)Lq * Dq,              // C: g_F0a [j][d]
        Lq, Lq,
        -1, 0, -1, 0, -1, -1);

    // 3b) F1a = A @ W1     [NN gemm: A [m=i][k=j] transpose-load, W1 direct]
    gemm_kernel<0, 1, 0><<<dim3(4, 4, Bq), 256>>>(
        2, nullptr, Lq, (long)Lq * Lq,     // A op: g_A [i][j] as [m][k]
        -1, W1, Dq, 0L,                    // B op: W1 [j][d] as [k][n], shared
        4, Dq, (long)Lq * Dq,              // C: g_F1a [i][d]
        Lq, Lq,
        -1, 0, -1, 0, -1, -1);

    // 4) conv + tanh + row norms  -> out0/out1 [B, CUR, D], m0/m1
    conv_tanh_kernel<<<dim3(CUR, Bq, 2), 128>>>(cw, cb);

    // 5) zero A2 row/col sum accumulators
    zero_sums_kernel<<<(Bq * CUR + 255) / 256, 256>>>();

    // 6) A2 = 1/(1+dist(out0,out1)); accumulate row sums (a0) and col sums (a1)
    gemm_kernel<0, 0, 2><<<dim3(5, 5, Bq), 256>>>(
        5, nullptr, Dq, (long)CUR * Dq,    // A op: g_out0 [s][d]
        6, nullptr, Dq, (long)CUR * Dq,    // B op: g_out1 [t][d]
        0, 0, 0L,                          // C unused
        CUR, CUR,
        9, CUR, 10, CUR,                   // norms g_m0, g_m1
        11, 12);                           // sums  g_a0, g_a1

    // 7) weighted average pool -> d_out (o0 then o1)
    pool_kernel<<<dim3(Lq, Bq, 2), 128>>>(outp);

    (void)in_sizes; (void)n_in; (void)out_size;
}

// round 3
// speedup vs baseline: 2.3259x; 2.3259x over previous
#include <cuda_runtime.h>
#include <cstdint>
#include <math.h>

#define Bq  64
#define Lq  512
#define Dq  512
#define Wq  4
#define CUR 515   // L + W - 1
#define PAD 20    // smem row stride in floats (conflict-free, 16B-aligned)

// ---------------------------------------------------------------------------
// Device-global scratch
// ---------------------------------------------------------------------------
__device__ float g_F0 [Bq * Lq * Dq];
__device__ float g_F1 [Bq * Lq * Dq];
__device__ float g_A  [Bq * Lq * Lq];
__device__ float g_F0a[Bq * Lq * Dq];
__device__ float g_F1a[Bq * Lq * Dq];
__device__ float g_out0[Bq * CUR * Dq];
__device__ float g_out1[Bq * CUR * Dq];
__device__ float g_n0 [Bq * Lq];
__device__ float g_n1 [Bq * Lq];
__device__ float g_m0 [Bq * CUR];
__device__ float g_m1 [Bq * CUR];
__device__ float g_a0 [Bq * CUR];
__device__ float g_a1 [Bq * CUR];
__device__ float g_At [Bq * Lq * Lq];   // transpose of g_A
__device__ float g_W0t[Dq * Lq];        // W0^T (tf32-rounded)
__device__ float g_W1t[Dq * Lq];        // W1^T (tf32-rounded)

__device__ __forceinline__ float* buf_ptr(int id) {
    switch (id) {
        case 0:  return g_F0;
        case 1:  return g_F1;
        case 2:  return g_A;
        case 3:  return g_F0a;
        case 4:  return g_F1a;
        case 5:  return g_out0;
        case 6:  return g_out1;
        case 7:  return g_n0;
        case 8:  return g_n1;
        case 9:  return g_m0;
        case 10: return g_m1;
        case 11: return g_a0;
        case 12: return g_a1;
        case 13: return g_At;
        case 14: return g_W0t;
        case 15: return g_W1t;
    }
    return nullptr;
}

__device__ __forceinline__ float rnd_tf32(float x) {
    uint32_t u;
    asm("cvt.rna.tf32.f32 %0, %1;" : "=r"(u) : "f"(x));
    return __uint_as_float(u);
}

__device__ __forceinline__ unsigned smem_u32(const void* p) {
    return (unsigned)__cvta_generic_to_shared(p);
}

#define CP16(smem_b, gptr) \
    asm volatile("cp.async.cg.shared.global [%0], [%1], 16;" :: "r"(smem_b), "l"(gptr))
#define CP_COMMIT()  asm volatile("cp.async.commit_group;" ::)
#define MMA_TF32(c, a, b0v, b1v) \
    asm volatile("mma.sync.aligned.m16n8k8.row.col.f32.tf32.tf32.f32 " \
        "{%0,%1,%2,%3},{%4,%5,%6,%7},{%8,%9},{%0,%1,%2,%3};" \
        : "+f"(c[0]), "+f"(c[1]), "+f"(c[2]), "+f"(c[3]) \
        : "r"(a[0]), "r"(a[1]), "r"(a[2]), "r"(a[3]), "r"(b0v), "r"(b1v))

// ---------------------------------------------------------------------------
// mask + tf32-round + row sq-norms
// ---------------------------------------------------------------------------
__global__ void mask_norm_kernel(const float* __restrict__ F0r,
                                 const float* __restrict__ F1r,
                                 const float* __restrict__ msk0,
                                 const float* __restrict__ msk1)
{
    const int i     = blockIdx.x;
    const int b     = blockIdx.y;
    const int which = blockIdx.z;

    const float* src = which ? F1r  : F0r;
    const float* msk = which ? msk1 : msk0;
    float*       dst = which ? g_F1 : g_F0;
    float*       nrm = which ? g_n1 : g_n0;

    const float m = msk[b * Lq + i];
    const long  base = ((long)b * Lq + i) * Dq + threadIdx.x * 4;

    float4 v = *(const float4*)(src + base);
    v.x = rnd_tf32(v.x * m); v.y = rnd_tf32(v.y * m);
    v.z = rnd_tf32(v.z * m); v.w = rnd_tf32(v.w * m);
    *(float4*)(dst + base) = v;

    float s = v.x * v.x + v.y * v.y + v.z * v.z + v.w * v.w;
#pragma unroll
    for (int off = 16; off > 0; off >>= 1)
        s += __shfl_xor_sync(0xffffffffu, s, off);

    __shared__ float red[4];
    const int lane = threadIdx.x & 31;
    const int wrp  = threadIdx.x >> 5;
    if (lane == 0) red[wrp] = s;
    __syncthreads();
    if (threadIdx.x == 0)
        nrm[b * Lq + i] = red[0] + red[1] + red[2] + red[3];
}

// ---------------------------------------------------------------------------
// W0/W1 transpose + tf32 round :  g_Wxt[d][i] = rnd(Wx[i][d])
// ---------------------------------------------------------------------------
__global__ void prep_w_kernel(const float* __restrict__ W0,
                              const float* __restrict__ W1)
{
    __shared__ float tile[32][33];
    const int which = blockIdx.z;
    const float* W  = which ? W1 : W0;
    float*       Wt = which ? g_W1t : g_W0t;
    const int i0 = blockIdx.y * 32, d0 = blockIdx.x * 32;

    for (int r = threadIdx.y; r < 32; r += 8)
        tile[r][threadIdx.x] = W[(i0 + r) * Dq + d0 + threadIdx.x];
    __syncthreads();
    for (int r = threadIdx.y; r < 32; r += 8)
        Wt[(d0 + r) * Lq + i0 + threadIdx.x] = rnd_tf32(tile[threadIdx.x][r]);
}

// ---------------------------------------------------------------------------
// tf32 tensor-core GEMM, all-NT (C[m][n] = sum_k Am[m][k]*Bm[n][k]), K=512.
// 128x128 blocktile, 8 warps (2x4), 64x32 warptiles, k-tile 16, 2-stage cp.async.
// Fragments loaded with plain LDS from pad-20 smem (documented mma layouts).
// EPI: 0 plain C, 1 distance->C and C^T (tf32-rounded), 2 distance->row/col sums.
// ---------------------------------------------------------------------------
template <int EPI, bool GUARD>
__global__ __launch_bounds__(256, 2)
void mma_gemm(int aId, long aB, int bId, long bB, int cId, long cB,
              int rnId, int rnB, int cnId, int cnB,
              int rsId, int csId, int ctId, int M, int N)
{
    // stage layout: A[128*PAD] then B[128*PAD]; 2 stages
    __shared__ float sm[2][2 * 128 * PAD];

    const int b  = blockIdx.z;
    const int m0 = blockIdx.y * 128, n0 = blockIdx.x * 128;
    const float* Ap = buf_ptr(aId) + (long)b * aB;
    const float* Bp = buf_ptr(bId) + (long)b * bB;

    const int tid  = threadIdx.x;
    const int warp = tid >> 5, lane = tid & 31;
    const int wm = (warp >> 2) * 64;   // 0 or 64
    const int wn = (warp & 3) * 32;    // 0..96
    const int g  = lane >> 2;          // groupID 0..7
    const int tg = lane & 3;           // thread-in-group 0..3

    // loader mapping: row = tid>>1, chunk base col = (tid&1)*8 (two 16B chunks)
    const int lr = tid >> 1;
    const int lc = (tid & 1) * 8;
    const bool aV = !GUARD || (m0 + lr < M);
    const bool bV = !GUARD || (n0 + lr < N);
    const float* aSrc = Ap + (long)(m0 + lr) * 512 + lc;
    const float* bSrc = Bp + (long)(n0 + lr) * 512 + lc;

    float acc[4][4][4];
#pragma unroll
    for (int mi = 0; mi < 4; mi++)
#pragma unroll
        for (int ni = 0; ni < 4; ni++)
#pragma unroll
            for (int q = 0; q < 4; q++) acc[mi][ni][q] = 0.f;

    auto load_stage = [&](int s, int k0) {
        float* As = sm[s];
        float* Bs = sm[s] + 128 * PAD;
        if (aV) {
            unsigned d = smem_u32(As + lr * PAD + lc);
            CP16(d, aSrc + k0);
            CP16(d + 16, aSrc + k0 + 4);
        } else {
            *(float4*)(As + lr * PAD + lc)     = make_float4(0, 0, 0, 0);
            *(float4*)(As + lr * PAD + lc + 4) = make_float4(0, 0, 0, 0);
        }
        if (bV) {
            unsigned d = smem_u32(Bs + lr * PAD + lc);
            CP16(d, bSrc + k0);
            CP16(d + 16, bSrc + k0 + 4);
        } else {
            *(float4*)(Bs + lr * PAD + lc)     = make_float4(0, 0, 0, 0);
            *(float4*)(Bs + lr * PAD + lc + 4) = make_float4(0, 0, 0, 0);
        }
    };

    load_stage(0, 0);
    CP_COMMIT();

    for (int it = 0; it < 32; ++it) {
        if (it + 1 < 32) {
            load_stage((it + 1) & 1, (it + 1) * 16);
            CP_COMMIT();
            asm volatile("cp.async.wait_group 1;" ::);
        } else {
            asm volatile("cp.async.wait_group 0;" ::);
        }
        __syncthreads();

        const float* As = sm[it & 1];
        const float* Bs = sm[it & 1] + 128 * PAD;

#pragma unroll
        for (int kk = 0; kk < 16; kk += 8) {
            // B fragments: b0 = Bs[n=wn+ni*8+g][kk+tg], b1 = [...][kk+tg+4]
            uint32_t bf[4][2];
#pragma unroll
            for (int ni = 0; ni < 4; ni++) {
                const float* p = Bs + (wn + ni * 8 + g) * PAD + kk + tg;
                bf[ni][0] = __float_as_uint(p[0]);
                bf[ni][1] = __float_as_uint(p[4]);
            }
            // A fragments: a0=[r][kk+tg], a1=[r+8][kk+tg], a2=[r][kk+tg+4], a3=[r+8][kk+tg+4]
            uint32_t af[4][4];
#pragma unroll
            for (int mi = 0; mi < 4; mi++) {
                const float* p = As + (wm + mi * 16 + g) * PAD + kk + tg;
                af[mi][0] = __float_as_uint(p[0]);
                af[mi][1] = __float_as_uint(p[8 * PAD]);
                af[mi][2] = __float_as_uint(p[4]);
                af[mi][3] = __float_as_uint(p[8 * PAD + 4]);
            }
#pragma unroll
            for (int mi = 0; mi < 4; mi++)
#pragma unroll
                for (int ni = 0; ni < 4; ni++)
                    MMA_TF32(acc[mi][ni], af[mi], bf[ni][0], bf[ni][1]);
        }
        __syncthreads();
    }

    // ---- epilogue ------------------------------------------------------
    const int rA = g;          // C row = groupID (plus +8 for c2/c3)
    const int cA = tg * 2;     // C col = 2*tig (+1)

    if (EPI == 0) {
        float* C = buf_ptr(cId) + (long)b * cB;
#pragma unroll
        for (int mi = 0; mi < 4; mi++) {
            const int r0 = m0 + wm + mi * 16 + rA;
#pragma unroll
            for (int ni = 0; ni < 4; ni++) {
                const int c0 = n0 + wn + ni * 8 + cA;
                *(float2*)&C[(long)r0 * 512 + c0] =
                    make_float2(acc[mi][ni][0], acc[mi][ni][1]);
                *(float2*)&C[(long)(r0 + 8) * 512 + c0] =
                    make_float2(acc[mi][ni][2], acc[mi][ni][3]);
            }
        }
    } else if (EPI == 1) {
        const float* rn = buf_ptr(rnId) + (long)b * rnB;
        const float* cn = buf_ptr(cnId) + (long)b * cnB;
        float* C  = buf_ptr(cId) + (long)b * cB;
        float* Ct = buf_ptr(ctId) + (long)b * cB;
        float rv[4][2], cv[4][2];
#pragma unroll
        for (int mi = 0; mi < 4; mi++) {
            rv[mi][0] = rn[m0 + wm + mi * 16 + rA];
            rv[mi][1] = rn[m0 + wm + mi * 16 + rA + 8];
        }
#pragma unroll
        for (int ni = 0; ni < 4; ni++) {
            cv[ni][0] = cn[n0 + wn + ni * 8 + cA];
            cv[ni][1] = cn[n0 + wn + ni * 8 + cA + 1];
        }
#pragma unroll
        for (int mi = 0; mi < 4; mi++) {
            const int r0 = m0 + wm + mi * 16 + rA;
#pragma unroll
            for (int ni = 0; ni < 4; ni++) {
                const int c0 = n0 + wn + ni * 8 + cA;
                float o[4];
#pragma unroll
                for (int q = 0; q < 4; q++) {
                    const float sq = rv[mi][q >> 1] + cv[ni][q & 1]
                                   - 2.f * acc[mi][ni][q];
                    o[q] = rnd_tf32(1.f / (1.f + sqrtf(fmaxf(sq, 0.f))));
                }
                *(float2*)&C[(long)r0 * 512 + c0]       = make_float2(o[0], o[1]);
                *(float2*)&C[(long)(r0 + 8) * 512 + c0] = make_float2(o[2], o[3]);
                Ct[(long)c0 * 512 + r0]           = o[0];
                Ct[(long)(c0 + 1) * 512 + r0]     = o[1];
                Ct[(long)c0 * 512 + r0 + 8]       = o[2];
                Ct[(long)(c0 + 1) * 512 + r0 + 8] = o[3];
            }
        }
    } else {   // EPI == 2
        const float* rn = buf_ptr(rnId) + (long)b * rnB;
        const float* cn = buf_ptr(cnId) + (long)b * cnB;
        float rv[4][2], cv[4][2];
        float rs[4][2], cs[4][2];
#pragma unroll
        for (int mi = 0; mi < 4; mi++) {
            const int r0 = m0 + wm + mi * 16 + rA;
            rv[mi][0] = (r0 < M)     ? rn[r0]     : 0.f;
            rv[mi][1] = (r0 + 8 < M) ? rn[r0 + 8] : 0.f;
            rs[mi][0] = rs[mi][1] = 0.f;
        }
#pragma unroll
        for (int ni = 0; ni < 4; ni++) {
            const int c0 = n0 + wn + ni * 8 + cA;
            cv[ni][0] = (c0 < N)     ? cn[c0]     : 0.f;
            cv[ni][1] = (c0 + 1 < N) ? cn[c0 + 1] : 0.f;
            cs[ni][0] = cs[ni][1] = 0.f;
        }
#pragma unroll
        for (int mi = 0; mi < 4; mi++) {
            const int r0 = m0 + wm + mi * 16 + rA;
#pragma unroll
            for (int ni = 0; ni < 4; ni++) {
                const int c0 = n0 + wn + ni * 8 + cA;
#pragma unroll
                for (int q = 0; q < 4; q++) {
                    const int rr = q >> 1, cc = q & 1;
                    const int R = r0 + rr * 8, Cc = c0 + cc;
                    if (R < M && Cc < N) {
                        const float sq = rv[mi][rr] + cv[ni][cc]
                                       - 2.f * acc[mi][ni][q];
                        const float a2 = 1.f / (1.f + sqrtf(fmaxf(sq, 0.f)));
                        rs[mi][rr] += a2;
                        cs[ni][cc] += a2;
                    }
                }
            }
        }
        // row sums: reduce across tig (lanes xor 1,2)
#pragma unroll
        for (int mi = 0; mi < 4; mi++)
#pragma unroll
            for (int rr = 0; rr < 2; rr++) {
                rs[mi][rr] += __shfl_xor_sync(0xffffffffu, rs[mi][rr], 1);
                rs[mi][rr] += __shfl_xor_sync(0xffffffffu, rs[mi][rr], 2);
            }
        // col sums: reduce across groupID (lanes xor 4,8,16)
#pragma unroll
        for (int ni = 0; ni < 4; ni++)
#pragma unroll
            for (int cc = 0; cc < 2; cc++) {
                cs[ni][cc] += __shfl_xor_sync(0xffffffffu, cs[ni][cc], 4);
                cs[ni][cc] += __shfl_xor_sync(0xffffffffu, cs[ni][cc], 8);
                cs[ni][cc] += __shfl_xor_sync(0xffffffffu, cs[ni][cc], 16);
            }
        float* rsum = buf_ptr(rsId) + (long)b * CUR;
        float* csum = buf_ptr(csId) + (long)b * CUR;
        if (tg == 0) {
#pragma unroll
            for (int mi = 0; mi < 4; mi++) {
                const int r0 = m0 + wm + mi * 16 + rA;
                if (r0 < M)     atomicAdd(&rsum[r0],     rs[mi][0]);
                if (r0 + 8 < M) atomicAdd(&rsum[r0 + 8], rs[mi][1]);
            }
        }
        if (lane < 4) {
#pragma unroll
            for (int ni = 0; ni < 4; ni++) {
                const int c0 = n0 + wn + ni * 8 + lane * 2;
                if (c0 < N)     atomicAdd(&csum[c0],     cs[ni][0]);
                if (c0 + 1 < N) atomicAdd(&csum[c0 + 1], cs[ni][1]);
            }
        }
    }
}

// ---------------------------------------------------------------------------
// conv + tanh (+tf32 round) + row norms
// ---------------------------------------------------------------------------
__global__ void conv_tanh_kernel(const float* __restrict__ cw,
                                 const float* __restrict__ cb)
{
    const int t     = blockIdx.x;
    const int b     = blockIdx.y;
    const int which = blockIdx.z;

    const float* F   = which ? g_F1   : g_F0;
    const float* Fa  = which ? g_F1a  : g_F0a;
    float*       out = which ? g_out1 : g_out0;
    float*       mn  = which ? g_m1   : g_m0;

    float w0[4], w1[4];
#pragma unroll
    for (int k = 0; k < 4; k++) { w0[k] = cw[k]; w1[k] = cw[4 + k]; }
    const float bias = cb[0];

    const int d0 = threadIdx.x * 4;
    float4 acc = make_float4(bias, bias, bias, bias);
#pragma unroll
    for (int k = 0; k < 4; k++) {
        const int r = t + k - (Wq - 1);
        if (r >= 0 && r < Lq) {
            const long base = ((long)b * Lq + r) * Dq + d0;
            float4 f  = *(const float4*)(F  + base);
            float4 fa = *(const float4*)(Fa + base);
            acc.x = fmaf(w0[k], f.x, fmaf(w1[k], fa.x, acc.x));
            acc.y = fmaf(w0[k], f.y, fmaf(w1[k], fa.y, acc.y));
            acc.z = fmaf(w0[k], f.z, fmaf(w1[k], fa.z, acc.z));
            acc.w = fmaf(w0[k], f.w, fmaf(w1[k], fa.w, acc.w));
        }
    }
    acc.x = rnd_tf32(tanhf(acc.x)); acc.y = rnd_tf32(tanhf(acc.y));
    acc.z = rnd_tf32(tanhf(acc.z)); acc.w = rnd_tf32(tanhf(acc.w));
    *(float4*)(out + ((long)b * CUR + t) * Dq + d0) = acc;

    float s = acc.x * acc.x + acc.y * acc.y + acc.z * acc.z + acc.w * acc.w;
#pragma unroll
    for (int off = 16; off > 0; off >>= 1)
        s += __shfl_xor_sync(0xffffffffu, s, off);
    __shared__ float red[4];
    const int lane = threadIdx.x & 31;
    const int wrp  = threadIdx.x >> 5;
    if (lane == 0) red[wrp] = s;
    __syncthreads();
    if (threadIdx.x == 0)
        mn[b * CUR + t] = red[0] + red[1] + red[2] + red[3];
}

__global__ void zero_sums_kernel()
{
    const int i = blockIdx.x * blockDim.x + threadIdx.x;
    if (i < Bq * CUR) { g_a0[i] = 0.f; g_a1[i] = 0.f; }
}

__global__ void pool_kernel(float* __restrict__ outp)
{
    const int t     = blockIdx.x;
    const int b     = blockIdx.y;
    const int which = blockIdx.z;

    const float* src = which ? g_out1 : g_out0;
    const float* a   = which ? g_a1   : g_a0;

    const int d0 = threadIdx.x * 4;
    float4 acc = make_float4(0.f, 0.f, 0.f, 0.f);
#pragma unroll
    for (int k = 0; k < 4; k++) {
        const float w = a[b * CUR + t + k];
        float4 v = *(const float4*)(src + ((long)b * CUR + t + k) * Dq + d0);
        acc.x = fmaf(w, v.x, acc.x);
        acc.y = fmaf(w, v.y, acc.y);
        acc.z = fmaf(w, v.z, acc.z);
        acc.w = fmaf(w, v.w, acc.w);
    }
    acc.x *= 0.25f; acc.y *= 0.25f; acc.z *= 0.25f; acc.w *= 0.25f;

    float* dst = outp + (long)which * Bq * Lq * Dq + ((long)b * Lq + t) * Dq + d0;
    *(float4*)dst = acc;
}

// ---------------------------------------------------------------------------
extern "C" void kernel_launch(void* const* d_in, const int* in_sizes, int n_in,
                              void* d_out, int out_size)
{
    const float* F0r  = (const float*)d_in[0];
    const float* F1r  = (const float*)d_in[1];
    const float* sm0  = (const float*)d_in[2];
    const float* sm1  = (const float*)d_in[3];
    const float* W0   = (const float*)d_in[4];
    const float* W1   = (const float*)d_in[5];
    const float* cw   = (const float*)d_in[6];
    const float* cb   = (const float*)d_in[7];
    float*       outp = (float*)d_out;

    mask_norm_kernel<<<dim3(Lq, Bq, 2), 128>>>(F0r, F1r, sm0, sm1);
    prep_w_kernel<<<dim3(16, 16, 2), dim3(32, 8)>>>(W0, W1);

    // G1: A = 1/(1+dist(F0,F1)); writes g_A and g_At
    mma_gemm<1, false><<<dim3(4, 4, Bq), 256>>>(
        0, (long)Lq * Dq, 1, (long)Lq * Dq, 2, (long)Lq * Lq,
        7, Lq, 8, Lq, -1, -1, 13, Lq, Lq);

    // G2: F0a = A^T @ W0  (At x W0t, NT)
    mma_gemm<0, false><<<dim3(4, 4, Bq), 256>>>(
        13, (long)Lq * Lq, 14, 0L, 3, (long)Lq * Dq,
        -1, 0, -1, 0, -1, -1, -1, Lq, Dq);

    // G3: F1a = A @ W1  (A x W1t, NT)
    mma_gemm<0, false><<<dim3(4, 4, Bq), 256>>>(
        2, (long)Lq * Lq, 15, 0L, 4, (long)Lq * Dq,
        -1, 0, -1, 0, -1, -1, -1, Lq, Dq);

    conv_tanh_kernel<<<dim3(CUR, Bq, 2), 128>>>(cw, cb);
    zero_sums_kernel<<<(Bq * CUR + 255) / 256, 256>>>();

    // G4: A2 row/col sums
    mma_gemm<2, true><<<dim3(5, 5, Bq), 256>>>(
        5, (long)CUR * Dq, 6, (long)CUR * Dq, -1, 0L,
        9, CUR, 10, CUR, 11, 12, -1, CUR, CUR);

    pool_kernel<<<dim3(Lq, Bq, 2), 128>>>(outp);

    (void)in_sizes; (void)n_in; (void)out_size;
}

// round 5
// speedup vs baseline: 2.3314x; 1.0023x over previous
#include <cuda_runtime.h>
#include <cstdint>
#include <math.h>

#define Bq  64
#define Lq  512
#define Dq  512
#define Wq  4
#define CUR 515   // L + W - 1
#define PAD 20    // NT smem row stride in floats (conflict-free, 16B-aligned)
#define TPAD 132  // TRANS smem row stride in floats (banks (4*tg+g)%32 distinct)

// ---------------------------------------------------------------------------
// Device-global scratch
// ---------------------------------------------------------------------------
__device__ float g_F0 [Bq * Lq * Dq];
__device__ float g_F1 [Bq * Lq * Dq];
__device__ float g_A  [Bq * Lq * Lq];
__device__ float g_F0a[Bq * Lq * Dq];
__device__ float g_F1a[Bq * Lq * Dq];
__device__ float g_out0[Bq * CUR * Dq];
__device__ float g_out1[Bq * CUR * Dq];
__device__ float g_n0 [Bq * Lq];
__device__ float g_n1 [Bq * Lq];
__device__ float g_m0 [Bq * CUR];
__device__ float g_m1 [Bq * CUR];
__device__ float g_a0 [Bq * CUR];
__device__ float g_a1 [Bq * CUR];
__device__ float g_W0t[Dq * Lq];        // W0^T (tf32-rounded)
__device__ float g_W1t[Dq * Lq];        // W1^T (tf32-rounded)

__device__ __forceinline__ float* buf_ptr(int id) {
    switch (id) {
        case 0:  return g_F0;
        case 1:  return g_F1;
        case 2:  return g_A;
        case 3:  return g_F0a;
        case 4:  return g_F1a;
        case 5:  return g_out0;
        case 6:  return g_out1;
        case 7:  return g_n0;
        case 8:  return g_n1;
        case 9:  return g_m0;
        case 10: return g_m1;
        case 11: return g_a0;
        case 12: return g_a1;
        case 14: return g_W0t;
        case 15: return g_W1t;
    }
    return nullptr;
}

__device__ __forceinline__ float rnd_tf32(float x) {
    uint32_t u;
    asm("cvt.rna.tf32.f32 %0, %1;" : "=r"(u) : "f"(x));
    return __uint_as_float(u);
}

__device__ __forceinline__ unsigned smem_u32(const void* p) {
    return (unsigned)__cvta_generic_to_shared(p);
}

#define CP16(smem_b, gptr) \
    asm volatile("cp.async.cg.shared.global [%0], [%1], 16;" :: "r"(smem_b), "l"(gptr))
#define CP_COMMIT()  asm volatile("cp.async.commit_group;" ::)
#define MMA_TF32(c, a, b0v, b1v) \
    asm volatile("mma.sync.aligned.m16n8k8.row.col.f32.tf32.tf32.f32 " \
        "{%0,%1,%2,%3},{%4,%5,%6,%7},{%8,%9},{%0,%1,%2,%3};" \
        : "+f"(c[0]), "+f"(c[1]), "+f"(c[2]), "+f"(c[3]) \
        : "r"(a[0]), "r"(a[1]), "r"(a[2]), "r"(a[3]), "r"(b0v), "r"(b1v))

// ---------------------------------------------------------------------------
// mask + tf32-round + row sq-norms
// ---------------------------------------------------------------------------
__global__ void mask_norm_kernel(const float* __restrict__ F0r,
                                 const float* __restrict__ F1r,
                                 const float* __restrict__ msk0,
                                 const float* __restrict__ msk1)
{
    const int i     = blockIdx.x;
    const int b     = blockIdx.y;
    const int which = blockIdx.z;

    const float* src = which ? F1r  : F0r;
    const float* msk = which ? msk1 : msk0;
    float*       dst = which ? g_F1 : g_F0;
    float*       nrm = which ? g_n1 : g_n0;

    const float m = msk[b * Lq + i];
    const long  base = ((long)b * Lq + i) * Dq + threadIdx.x * 4;

    float4 v = *(const float4*)(src + base);
    v.x = rnd_tf32(v.x * m); v.y = rnd_tf32(v.y * m);
    v.z = rnd_tf32(v.z * m); v.w = rnd_tf32(v.w * m);
    *(float4*)(dst + base) = v;

    float s = v.x * v.x + v.y * v.y + v.z * v.z + v.w * v.w;
#pragma unroll
    for (int off = 16; off > 0; off >>= 1)
        s += __shfl_xor_sync(0xffffffffu, s, off);

    __shared__ float red[4];
    const int lane = threadIdx.x & 31;
    const int wrp  = threadIdx.x >> 5;
    if (lane == 0) red[wrp] = s;
    __syncthreads();
    if (threadIdx.x == 0)
        nrm[b * Lq + i] = red[0] + red[1] + red[2] + red[3];
}

// ---------------------------------------------------------------------------
// W0/W1 transpose + tf32 round :  g_Wxt[d][i] = rnd(Wx[i][d])
// ---------------------------------------------------------------------------
__global__ void prep_w_kernel(const float* __restrict__ W0,
                              const float* __restrict__ W1)
{
    __shared__ float tile[32][33];
    const int which = blockIdx.z;
    const float* W  = which ? W1 : W0;
    float*       Wt = which ? g_W1t : g_W0t;
    const int i0 = blockIdx.y * 32, d0 = blockIdx.x * 32;

    for (int r = threadIdx.y; r < 32; r += 8)
        tile[r][threadIdx.x] = W[(i0 + r) * Dq + d0 + threadIdx.x];
    __syncthreads();
    for (int r = threadIdx.y; r < 32; r += 8)
        Wt[(d0 + r) * Lq + i0 + threadIdx.x] = rnd_tf32(tile[threadIdx.x][r]);
}

// ---------------------------------------------------------------------------
// tf32 tensor-core GEMM: C[m][n] = sum_k opA[m][k] * B[n][k], K = 512.
// 128x128 blocktile, 8 warps (2x4), 64x32 warptiles, k-tile 16, 2-stage cp.async
// (identical pipeline structure to the last known-good round).
// AMODE: 0 = A global [m][k] (NT); 1 = A global [k][m] (transposing loader).
// EPI: 0 plain C, 1 distance->C (tf32-rounded), 2 distance->row/col sums.
// ---------------------------------------------------------------------------
template <int EPI, int AMODE, bool GUARD>
__global__ __launch_bounds__(256, 2)
void mma_gemm(int aId, long aB, int bId, long bB, int cId, long cB,
              int rnId, int rnB, int cnId, int cnB,
              int rsId, int csId, int M, int N)
{
    // per stage: A region 2560 floats, B region 2560 floats
    __shared__ float sm[2][2 * 128 * PAD];

    const int b  = blockIdx.z;
    const int m0 = blockIdx.y * 128, n0 = blockIdx.x * 128;
    const float* Ap = buf_ptr(aId) + (long)b * aB;
    const float* Bp = buf_ptr(bId) + (long)b * bB;

    const int tid  = threadIdx.x;
    const int warp = tid >> 5, lane = tid & 31;
    const int wm = (warp >> 2) * 64;   // 0 or 64
    const int wn = (warp & 3) * 32;    // 0..96
    const int g  = lane >> 2;          // groupID 0..7
    const int tg = lane & 3;           // thread-in-group 0..3

    // NT loader mapping: row = tid>>1, chunk base col = (tid&1)*8
    const int lr = tid >> 1;
    const int lc = (tid & 1) * 8;
    const bool aV = !GUARD || (m0 + lr < M);
    const bool bV = !GUARD || (n0 + lr < N);
    const float* aSrcNT = Ap + (long)(m0 + lr) * 512 + lc;
    const float* bSrcNT = Bp + (long)(n0 + lr) * 512 + lc;
    // TRANS loader mapping: k-row = tid>>4 (0..15), m chunk = (tid&15)*8
    const int tkt = tid >> 4;
    const int tmc = (tid & 15) * 8;

    float acc[4][4][4];
#pragma unroll
    for (int mi = 0; mi < 4; mi++)
#pragma unroll
        for (int ni = 0; ni < 4; ni++)
#pragma unroll
            for (int q = 0; q < 4; q++) acc[mi][ni][q] = 0.f;

    auto load_stage = [&](int s, int k0) {
        float* As = sm[s];
        float* Bs = sm[s] + 128 * PAD;
        if (AMODE == 0) {
            if (aV) {
                unsigned d = smem_u32(As + lr * PAD + lc);
                CP16(d, aSrcNT + k0);
                CP16(d + 16, aSrcNT + k0 + 4);
            } else {
                *(float4*)(As + lr * PAD + lc)     = make_float4(0, 0, 0, 0);
                *(float4*)(As + lr * PAD + lc + 4) = make_float4(0, 0, 0, 0);
            }
        } else {
            const float* src = Ap + (long)(k0 + tkt) * 512 + m0 + tmc;
            unsigned d = smem_u32(As + tkt * TPAD + tmc);
            CP16(d, src);
            CP16(d + 16, src + 4);
        }
        if (bV) {
            unsigned d = smem_u32(Bs + lr * PAD + lc);
            CP16(d, bSrcNT + k0);
            CP16(d + 16, bSrcNT + k0 + 4);
        } else {
            *(float4*)(Bs + lr * PAD + lc)     = make_float4(0, 0, 0, 0);
            *(float4*)(Bs + lr * PAD + lc + 4) = make_float4(0, 0, 0, 0);
        }
    };

    load_stage(0, 0);
    CP_COMMIT();

    for (int it = 0; it < 32; ++it) {
        if (it + 1 < 32) {
            load_stage((it + 1) & 1, (it + 1) * 16);
            CP_COMMIT();
            asm volatile("cp.async.wait_group 1;" ::);
        } else {
            asm volatile("cp.async.wait_group 0;" ::);
        }
        __syncthreads();

        const float* As = sm[it & 1];
        const float* Bs = sm[it & 1] + 128 * PAD;

#pragma unroll
        for (int kk = 0; kk < 16; kk += 8) {
            uint32_t bf[4][2];
#pragma unroll
            for (int ni = 0; ni < 4; ni++) {
                const float* p = Bs + (wn + ni * 8 + g) * PAD + kk + tg;
                bf[ni][0] = __float_as_uint(p[0]);
                bf[ni][1] = __float_as_uint(p[4]);
            }
            uint32_t af[4][4];
#pragma unroll
            for (int mi = 0; mi < 4; mi++) {
                if (AMODE == 0) {
                    const float* p = As + (wm + mi * 16 + g) * PAD + kk + tg;
                    af[mi][0] = __float_as_uint(p[0]);
                    af[mi][1] = __float_as_uint(p[8 * PAD]);
                    af[mi][2] = __float_as_uint(p[4]);
                    af[mi][3] = __float_as_uint(p[8 * PAD + 4]);
                } else {
                    const float* p = As + (kk + tg) * TPAD + wm + mi * 16 + g;
                    af[mi][0] = __float_as_uint(p[0]);
                    af[mi][1] = __float_as_uint(p[8]);
                    af[mi][2] = __float_as_uint(p[4 * TPAD]);
                    af[mi][3] = __float_as_uint(p[4 * TPAD + 8]);
                }
            }
#pragma unroll
            for (int mi = 0; mi < 4; mi++)
#pragma unroll
                for (int ni = 0; ni < 4; ni++)
                    MMA_TF32(acc[mi][ni], af[mi], bf[ni][0], bf[ni][1]);
        }
        __syncthreads();
    }

    // ---- epilogue ------------------------------------------------------
    const int rA = g;          // C row = groupID (plus +8 for c2/c3)
    const int cA = tg * 2;     // C col = 2*tig (+1)

    if (EPI == 0) {
        float* C = buf_ptr(cId) + (long)b * cB;
#pragma unroll
        for (int mi = 0; mi < 4; mi++) {
            const int r0 = m0 + wm + mi * 16 + rA;
#pragma unroll
            for (int ni = 0; ni < 4; ni++) {
                const int c0 = n0 + wn + ni * 8 + cA;
                *(float2*)&C[(long)r0 * 512 + c0] =
                    make_float2(acc[mi][ni][0], acc[mi][ni][1]);
                *(float2*)&C[(long)(r0 + 8) * 512 + c0] =
                    make_float2(acc[mi][ni][2], acc[mi][ni][3]);
            }
        }
    } else if (EPI == 1) {
        const float* rn = buf_ptr(rnId) + (long)b * rnB;
        const float* cn = buf_ptr(cnId) + (long)b * cnB;
        float* C  = buf_ptr(cId) + (long)b * cB;
        float rv[4][2], cv[4][2];
#pragma unroll
        for (int mi = 0; mi < 4; mi++) {
            rv[mi][0] = rn[m0 + wm + mi * 16 + rA];
            rv[mi][1] = rn[m0 + wm + mi * 16 + rA + 8];
        }
#pragma unroll
        for (int ni = 0; ni < 4; ni++) {
            cv[ni][0] = cn[n0 + wn + ni * 8 + cA];
            cv[ni][1] = cn[n0 + wn + ni * 8 + cA + 1];
        }
#pragma unroll
        for (int mi = 0; mi < 4; mi++) {
            const int r0 = m0 + wm + mi * 16 + rA;
#pragma unroll
            for (int ni = 0; ni < 4; ni++) {
                const int c0 = n0 + wn + ni * 8 + cA;
                float o[4];
#pragma unroll
                for (int q = 0; q < 4; q++) {
                    const float sq = rv[mi][q >> 1] + cv[ni][q & 1]
                                   - 2.f * acc[mi][ni][q];
                    o[q] = rnd_tf32(1.f / (1.f + sqrtf(fmaxf(sq, 0.f))));
                }
                *(float2*)&C[(long)r0 * 512 + c0]       = make_float2(o[0], o[1]);
                *(float2*)&C[(long)(r0 + 8) * 512 + c0] = make_float2(o[2], o[3]);
            }
        }
    } else {   // EPI == 2
        const float* rn = buf_ptr(rnId) + (long)b * rnB;
        const float* cn = buf_ptr(cnId) + (long)b * cnB;
        float rv[4][2], cv[4][2];
        float rs[4][2], cs[4][2];
#pragma unroll
        for (int mi = 0; mi < 4; mi++) {
            const int r0 = m0 + wm + mi * 16 + rA;
            rv[mi][0] = (r0 < M)     ? rn[r0]     : 0.f;
            rv[mi][1] = (r0 + 8 < M) ? rn[r0 + 8] : 0.f;
            rs[mi][0] = rs[mi][1] = 0.f;
        }
#pragma unroll
        for (int ni = 0; ni < 4; ni++) {
            const int c0 = n0 + wn + ni * 8 + cA;
            cv[ni][0] = (c0 < N)     ? cn[c0]     : 0.f;
            cv[ni][1] = (c0 + 1 < N) ? cn[c0 + 1] : 0.f;
            cs[ni][0] = cs[ni][1] = 0.f;
        }
#pragma unroll
        for (int mi = 0; mi < 4; mi++) {
            const int r0 = m0 + wm + mi * 16 + rA;
#pragma unroll
            for (int ni = 0; ni < 4; ni++) {
                const int c0 = n0 + wn + ni * 8 + cA;
#pragma unroll
                for (int q = 0; q < 4; q++) {
                    const int rr = q >> 1, cc = q & 1;
                    const int R = r0 + rr * 8, Cc = c0 + cc;
                    if (R < M && Cc < N) {
                        const float sq = rv[mi][rr] + cv[ni][cc]
                                       - 2.f * acc[mi][ni][q];
                        const float a2 = 1.f / (1.f + sqrtf(fmaxf(sq, 0.f)));
                        rs[mi][rr] += a2;
                        cs[ni][cc] += a2;
                    }
                }
            }
        }
#pragma unroll
        for (int mi = 0; mi < 4; mi++)
#pragma unroll
            for (int rr = 0; rr < 2; rr++) {
                rs[mi][rr] += __shfl_xor_sync(0xffffffffu, rs[mi][rr], 1);
                rs[mi][rr] += __shfl_xor_sync(0xffffffffu, rs[mi][rr], 2);
            }
#pragma unroll
        for (int ni = 0; ni < 4; ni++)
#pragma unroll
            for (int cc = 0; cc < 2; cc++) {
                cs[ni][cc] += __shfl_xor_sync(0xffffffffu, cs[ni][cc], 4);
                cs[ni][cc] += __shfl_xor_sync(0xffffffffu, cs[ni][cc], 8);
                cs[ni][cc] += __shfl_xor_sync(0xffffffffu, cs[ni][cc], 16);
            }
        float* rsum = buf_ptr(rsId) + (long)b * CUR;
        float* csum = buf_ptr(csId) + (long)b * CUR;
        if (tg == 0) {
#pragma unroll
            for (int mi = 0; mi < 4; mi++) {
                const int r0 = m0 + wm + mi * 16 + rA;
                if (r0 < M)     atomicAdd(&rsum[r0],     rs[mi][0]);
                if (r0 + 8 < M) atomicAdd(&rsum[r0 + 8], rs[mi][1]);
            }
        }
        if (lane < 4) {
#pragma unroll
            for (int ni = 0; ni < 4; ni++) {
                const int c0 = n0 + wn + ni * 8 + lane * 2;
                if (c0 < N)     atomicAdd(&csum[c0],     cs[ni][0]);
                if (c0 + 1 < N) atomicAdd(&csum[c0 + 1], cs[ni][1]);
            }
        }
    }
}

// ---------------------------------------------------------------------------
// conv + tanh (+tf32 round) + row norms
// ---------------------------------------------------------------------------
__global__ void conv_tanh_kernel(const float* __restrict__ cw,
                                 const float* __restrict__ cb)
{
    const int t     = blockIdx.x;
    const int b     = blockIdx.y;
    const int which = blockIdx.z;

    const float* F   = which ? g_F1   : g_F0;
    const float* Fa  = which ? g_F1a  : g_F0a;
    float*       out = which ? g_out1 : g_out0;
    float*       mn  = which ? g_m1   : g_m0;

    float w0[4], w1[4];
#pragma unroll
    for (int k = 0; k < 4; k++) { w0[k] = cw[k]; w1[k] = cw[4 + k]; }
    const float bias = cb[0];

    const int d0 = threadIdx.x * 4;
    float4 acc = make_float4(bias, bias, bias, bias);
#pragma unroll
    for (int k = 0; k < 4; k++) {
        const int r = t + k - (Wq - 1);
        if (r >= 0 && r < Lq) {
            const long base = ((long)b * Lq + r) * Dq + d0;
            float4 f  = *(const float4*)(F  + base);
            float4 fa = *(const float4*)(Fa + base);
            acc.x = fmaf(w0[k], f.x, fmaf(w1[k], fa.x, acc.x));
            acc.y = fmaf(w0[k], f.y, fmaf(w1[k], fa.y, acc.y));
            acc.z = fmaf(w0[k], f.z, fmaf(w1[k], fa.z, acc.z));
            acc.w = fmaf(w0[k], f.w, fmaf(w1[k], fa.w, acc.w));
        }
    }
    acc.x = rnd_tf32(tanhf(acc.x)); acc.y = rnd_tf32(tanhf(acc.y));
    acc.z = rnd_tf32(tanhf(acc.z)); acc.w = rnd_tf32(tanhf(acc.w));
    *(float4*)(out + ((long)b * CUR + t) * Dq + d0) = acc;

    float s = acc.x * acc.x + acc.y * acc.y + acc.z * acc.z + acc.w * acc.w;
#pragma unroll
    for (int off = 16; off > 0; off >>= 1)
        s += __shfl_xor_sync(0xffffffffu, s, off);
    __shared__ float red[4];
    const int lane = threadIdx.x & 31;
    const int wrp  = threadIdx.x >> 5;
    if (lane == 0) red[wrp] = s;
    __syncthreads();
    if (threadIdx.x == 0)
        mn[b * CUR + t] = red[0] + red[1] + red[2] + red[3];
}

__global__ void zero_sums_kernel()
{
    const int i = blockIdx.x * blockDim.x + threadIdx.x;
    if (i < Bq * CUR) { g_a0[i] = 0.f; g_a1[i] = 0.f; }
}

__global__ void pool_kernel(float* __restrict__ outp)
{
    const int t     = blockIdx.x;
    const int b     = blockIdx.y;
    const int which = blockIdx.z;

    const float* src = which ? g_out1 : g_out0;
    const float* a   = which ? g_a1   : g_a0;

    const int d0 = threadIdx.x * 4;
    float4 acc = make_float4(0.f, 0.f, 0.f, 0.f);
#pragma unroll
    for (int k = 0; k < 4; k++) {
        const float w = a[b * CUR + t + k];
        float4 v = *(const float4*)(src + ((long)b * CUR + t + k) * Dq + d0);
        acc.x = fmaf(w, v.x, acc.x);
        acc.y = fmaf(w, v.y, acc.y);
        acc.z = fmaf(w, v.z, acc.z);
        acc.w = fmaf(w, v.w, acc.w);
    }
    acc.x *= 0.25f; acc.y *= 0.25f; acc.z *= 0.25f; acc.w *= 0.25f;

    float* dst = outp + (long)which * Bq * Lq * Dq + ((long)b * Lq + t) * Dq + d0;
    *(float4*)dst = acc;
}

// ---------------------------------------------------------------------------
extern "C" void kernel_launch(void* const* d_in, const int* in_sizes, int n_in,
                              void* d_out, int out_size)
{
    const float* F0r  = (const float*)d_in[0];
    const float* F1r  = (const float*)d_in[1];
    const float* sm0  = (const float*)d_in[2];
    const float* sm1  = (const float*)d_in[3];
    const float* W0   = (const float*)d_in[4];
    const float* W1   = (const float*)d_in[5];
    const float* cw   = (const float*)d_in[6];
    const float* cb   = (const float*)d_in[7];
    float*       outp = (float*)d_out;

    mask_norm_kernel<<<dim3(Lq, Bq, 2), 128>>>(F0r, F1r, sm0, sm1);
    prep_w_kernel<<<dim3(16, 16, 2), dim3(32, 8)>>>(W0, W1);

    // G1: A = 1/(1+dist(F0,F1)) -> g_A   (NT, distance epilogue, no transpose)
    mma_gemm<1, 0, false><<<dim3(4, 4, Bq), 256>>>(
        0, (long)Lq * Dq, 1, (long)Lq * Dq, 2, (long)Lq * Lq,
        7, Lq, 8, Lq, -1, -1, Lq, Lq);

    // G2: F0a[j][d] = sum_i A[i][j] * W0t[d][i]   (A via transposing loader)
    mma_gemm<0, 1, false><<<dim3(4, 4, Bq), 256>>>(
        2, (long)Lq * Lq, 14, 0L, 3, (long)Lq * Dq,
        -1, 0, -1, 0, -1, -1, Lq, Dq);

    // G3: F1a[i][d] = sum_j A[i][j] * W1t[d][j]   (NT)
    mma_gemm<0, 0, false><<<dim3(4, 4, Bq), 256>>>(
        2, (long)Lq * Lq, 15, 0L, 4, (long)Lq * Dq,
        -1, 0, -1, 0, -1, -1, Lq, Dq);

    conv_tanh_kernel<<<dim3(CUR, Bq, 2), 128>>>(cw, cb);
    zero_sums_kernel<<<(Bq * CUR + 255) / 256, 256>>>();

    // G4: A2 row/col sums (guarded, distance+reduce epilogue)
    mma_gemm<2, 0, true><<<dim3(5, 5, Bq), 256>>>(
        5, (long)CUR * Dq, 6, (long)CUR * Dq, -1, 0L,
        9, CUR, 10, CUR, 11, 12, CUR, CUR);

    pool_kernel<<<dim3(Lq, Bq, 2), 128>>>(outp);

    (void)in_sizes; (void)n_in; (void)out_size;
}